// round 6
// baseline (speedup 1.0000x reference)
#include <cuda_runtime.h>
#include <cuda_fp16.h>

// ---------------------------------------------------------------------------
// GCN, weightless-CSR formulation:
//   hh1 = dinv * (x @ W1)            (dinv folded into GEMM epilogue)
//   g1  = relu(dinv * (hh1_self + sum_nbr hh1) + b1)
//   hh2 = dinv * (g1 @ W2)
//   pool += dinv * (hh2_self + sum_nbr hh2) + b2 ; out = pool / count
// CSR stores src indices only. Agg uses 16B/lane loads (2 or 4 edges per
// warp load) + shfl reduction; fp32 accumulation; fp16 feature storage.
// ---------------------------------------------------------------------------

#define NN 50000
#define NE 600000
#define NG 64
#define C_HID 128
#define C_OUT 64

#define CHUNK  200
#define NCHUNK 250           // 250 * 200 == 50000

// ------------------------- static device scratch ---------------------------
__device__ int   g_deg[NN];
__device__ float g_dinv[NN];
__device__ int   g_rowstart[NN + 1];
__device__ int   g_cursor[NN];
__device__ int   g_bsum[NCHUNK];
__device__ __align__(16) int    g_csr_src[NE];
__device__ __align__(16) __half g_h1[(size_t)NN * C_HID];   // dinv * (x @ W1)
__device__ __align__(16) __half g_g1[(size_t)NN * C_HID];   // relu layer-1 out
__device__ __align__(16) __half g_h2[(size_t)NN * C_OUT];   // dinv * (g1 @ W2)
__device__ __align__(16) float  g_pool[NG * C_OUT];

// ------------------------------- helpers -----------------------------------
__device__ __forceinline__ int lower_bound_i32(const int* __restrict__ a,
                                               int n, int v) {
    int lo = 0, hi = n;
    while (lo < hi) {
        int mid = (lo + hi) >> 1;
        if (a[mid] < v) lo = mid + 1; else hi = mid;
    }
    return lo;
}

__device__ __forceinline__ unsigned f2tf32(float f) {
    unsigned u;
    asm("cvt.rna.tf32.f32 %0, %1;" : "=r"(u) : "f"(f));
    return u;
}

__device__ __forceinline__ void mma_tf32(float* c, const unsigned* a,
                                         const unsigned* b) {
    asm volatile(
        "mma.sync.aligned.m16n8k8.row.col.f32.tf32.tf32.f32 "
        "{%0,%1,%2,%3}, {%4,%5,%6,%7}, {%8,%9}, {%0,%1,%2,%3};\n"
        : "+f"(c[0]), "+f"(c[1]), "+f"(c[2]), "+f"(c[3])
        : "r"(a[0]), "r"(a[1]), "r"(a[2]), "r"(a[3]), "r"(b[0]), "r"(b[1]));
}

__device__ __forceinline__ void acc_uint4(float* acc, uint4 v) {
    float2 f0 = __half22float2(*(const __half2*)&v.x);
    float2 f1 = __half22float2(*(const __half2*)&v.y);
    float2 f2 = __half22float2(*(const __half2*)&v.z);
    float2 f3 = __half22float2(*(const __half2*)&v.w);
    acc[0] += f0.x; acc[1] += f0.y; acc[2] += f1.x; acc[3] += f1.y;
    acc[4] += f2.x; acc[5] += f2.y; acc[6] += f3.x; acc[7] += f3.y;
}

// ------------------------------- kernels -----------------------------------

// degree of dst side; 4 edges per thread (int4 reads)
__global__ void k_deg(const int* __restrict__ ei) {
    int t = blockIdx.x * blockDim.x + threadIdx.x;
    int e4 = t * 4;
    if (e4 < NE) {
        int4 d = *(const int4*)(ei + NE + e4);
        atomicAdd(&g_deg[d.x], 1);
        atomicAdd(&g_deg[d.y], 1);
        atomicAdd(&g_deg[d.z], 1);
        atomicAdd(&g_deg[d.w], 1);
    }
}

// per-chunk exclusive scan of g_deg + dinv + chunk sums
__global__ void k_scanA() {
    __shared__ int s[256];
    int t = threadIdx.x;
    int idx = blockIdx.x * CHUNK + t;
    int v = (t < CHUNK) ? g_deg[idx] : 0;
    if (t < CHUNK) g_dinv[idx] = rsqrtf((float)(v + 1));
    s[t] = v;
    __syncthreads();
    #pragma unroll
    for (int off = 1; off < 256; off <<= 1) {
        int add = (t >= off) ? s[t - off] : 0;
        __syncthreads();
        s[t] += add;
        __syncthreads();
    }
    if (t < CHUNK) g_rowstart[idx] = s[t] - v;
    if (t == 255) g_bsum[blockIdx.x] = s[255];
}

// every block redundantly scans chunk sums, applies offsets, inits cursors
__global__ void k_scanC() {
    __shared__ int s[256];
    __shared__ int sbo[NCHUNK];
    int t = threadIdx.x;
    int v = (t < NCHUNK) ? g_bsum[t] : 0;
    s[t] = v;
    __syncthreads();
    #pragma unroll
    for (int off = 1; off < 256; off <<= 1) {
        int add = (t >= off) ? s[t - off] : 0;
        __syncthreads();
        s[t] += add;
        __syncthreads();
    }
    if (t < NCHUNK) sbo[t] = s[t] - v;
    __syncthreads();

    int i = blockIdx.x * blockDim.x + t;
    if (i < NN) {
        int r = g_rowstart[i] + sbo[i / CHUNK];
        g_rowstart[i] = r;
        g_cursor[i]   = r;
    }
    if (i == 0) g_rowstart[NN] = NE;
}

// fill CSR (indices only); 4 edges per thread
__global__ void k_fill(const int* __restrict__ ei) {
    int t = blockIdx.x * blockDim.x + threadIdx.x;
    int e4 = t * 4;
    if (e4 < NE) {
        int4 s = *(const int4*)(ei + e4);
        int4 d = *(const int4*)(ei + NE + e4);
        int p0 = atomicAdd(&g_cursor[d.x], 1);
        int p1 = atomicAdd(&g_cursor[d.y], 1);
        int p2 = atomicAdd(&g_cursor[d.z], 1);
        int p3 = atomicAdd(&g_cursor[d.w], 1);
        g_csr_src[p0] = s.x;
        g_csr_src[p1] = s.y;
        g_csr_src[p2] = s.z;
        g_csr_src[p3] = s.w;
    }
}

// --- tf32 GEMM: C[M,BN](fp16) = dinv[row] * (A[M,128] @ W[128,BN]) ----------
template<int BN, typename AT>
__global__ void __launch_bounds__(256)
k_gemm_tf32(const AT* __restrict__ A, const float* __restrict__ W,
            __half* __restrict__ C, int M) {
    constexpr int WN = BN / 2;
    constexpr int NT = WN / 8;
    __shared__ float As[128][20];
    __shared__ float Ws[BN][20];

    const int tid  = threadIdx.x;
    const int wid  = tid >> 5;
    const int lane = tid & 31;
    const int mw   = wid & 3;
    const int nw   = wid >> 2;
    const int row0 = blockIdx.x * 128;
    const int qr   = lane >> 2;
    const int qk   = lane & 3;

    float acc[2][NT][4];
    #pragma unroll
    for (int mt = 0; mt < 2; mt++)
        #pragma unroll
        for (int nt = 0; nt < NT; nt++)
            #pragma unroll
            for (int j = 0; j < 4; j++) acc[mt][nt][j] = 0.0f;

    for (int k0 = 0; k0 < 128; k0 += 16) {
        #pragma unroll
        for (int f = tid; f < 512; f += 256) {
            int r  = f >> 2;
            int k4 = (f & 3) * 4;
            int gr = row0 + r;
            float4 t = make_float4(0.f, 0.f, 0.f, 0.f);
            if (gr < M) {
                if constexpr (sizeof(AT) == 4) {
                    float4 v = *(const float4*)((const float*)A +
                                                (size_t)gr * 128 + k0 + k4);
                    t.x = __uint_as_float(f2tf32(v.x));
                    t.y = __uint_as_float(f2tf32(v.y));
                    t.z = __uint_as_float(f2tf32(v.z));
                    t.w = __uint_as_float(f2tf32(v.w));
                } else {
                    const __half2* p = (const __half2*)((const __half*)A +
                                                        (size_t)gr * 128 + k0 + k4);
                    float2 a = __half22float2(p[0]);
                    float2 b = __half22float2(p[1]);
                    t.x = a.x; t.y = a.y; t.z = b.x; t.w = b.y;
                }
            }
            *(float4*)&As[r][k4] = t;
        }
        #pragma unroll
        for (int f = tid; f < 16 * (BN / 4); f += 256) {
            int k  = f / (BN / 4);
            int n4 = (f % (BN / 4)) * 4;
            float4 v = *(const float4*)(W + (size_t)(k0 + k) * BN + n4);
            Ws[n4 + 0][k] = __uint_as_float(f2tf32(v.x));
            Ws[n4 + 1][k] = __uint_as_float(f2tf32(v.y));
            Ws[n4 + 2][k] = __uint_as_float(f2tf32(v.z));
            Ws[n4 + 3][k] = __uint_as_float(f2tf32(v.w));
        }
        __syncthreads();

        #pragma unroll
        for (int kk = 0; kk < 16; kk += 8) {
            unsigned afr[2][4];
            #pragma unroll
            for (int mt = 0; mt < 2; mt++) {
                int rb = mw * 32 + mt * 16;
                afr[mt][0] = __float_as_uint(As[rb + qr    ][kk + qk    ]);
                afr[mt][1] = __float_as_uint(As[rb + qr + 8][kk + qk    ]);
                afr[mt][2] = __float_as_uint(As[rb + qr    ][kk + qk + 4]);
                afr[mt][3] = __float_as_uint(As[rb + qr + 8][kk + qk + 4]);
            }
            #pragma unroll
            for (int nt = 0; nt < NT; nt++) {
                int nc = nw * WN + nt * 8 + qr;
                unsigned bfr[2];
                bfr[0] = __float_as_uint(Ws[nc][kk + qk    ]);
                bfr[1] = __float_as_uint(Ws[nc][kk + qk + 4]);
                mma_tf32(acc[0][nt], afr[0], bfr);
                mma_tf32(acc[1][nt], afr[1], bfr);
            }
        }
        __syncthreads();
    }

    // epilogue: scale rows by dinv, store fp16
    #pragma unroll
    for (int mt = 0; mt < 2; mt++) {
        int rb = row0 + mw * 32 + mt * 16 + qr;
        float d0 = (rb     < M) ? g_dinv[rb]     : 0.f;
        float d1 = (rb + 8 < M) ? g_dinv[rb + 8] : 0.f;
        #pragma unroll
        for (int nt = 0; nt < NT; nt++) {
            int col = nw * WN + nt * 8 + 2 * qk;
            if (rb < M)
                *(__half2*)(C + (size_t)rb * BN + col) =
                    __floats2half2_rn(acc[mt][nt][0] * d0, acc[mt][nt][1] * d0);
            if (rb + 8 < M)
                *(__half2*)(C + (size_t)(rb + 8) * BN + col) =
                    __floats2half2_rn(acc[mt][nt][2] * d1, acc[mt][nt][3] * d1);
        }
    }
}

// --------------- aggregation, C=128: one warp per dst node -----------------
// Row = 256B. Each lane loads uint4 (16B); half-warp covers a row => 2 edges
// per warp load. Virtual edge t=0 is the self row. shfl_xor(16) combines.
__global__ void k_agg128(const __half* __restrict__ h,
                         const float* __restrict__ bias,
                         __half* __restrict__ out) {
    int node = (blockIdx.x * blockDim.x + threadIdx.x) >> 5;
    if (node >= NN) return;
    int lane = threadIdx.x & 31;
    int hid  = lane >> 4;        // 0/1 : which edge of the pair
    int q    = lane & 15;        // 16B chunk within row
    const uint4* hv = (const uint4*)h;   // 16 uint4 per row

    int beg = g_rowstart[node];
    int cnt = g_rowstart[node + 1] - beg + 1;   // +1 virtual self
    float di = g_dinv[node];

    float acc[8];
    #pragma unroll
    for (int j = 0; j < 8; j++) acc[j] = 0.f;

    for (int base = 0; base < cnt; base += 4) {
        #pragma unroll
        for (int u = 0; u < 2; u++) {
            int t = base + u * 2 + hid;
            if (t < cnt) {
                int s = (t == 0) ? node : g_csr_src[beg + t - 1];
                acc_uint4(acc, hv[(size_t)s * 16 + q]);
            }
        }
    }
    #pragma unroll
    for (int j = 0; j < 8; j++)
        acc[j] += __shfl_xor_sync(0xffffffffu, acc[j], 16);

    if (hid == 0) {
        float4 b0 = ((const float4*)bias)[q * 2];
        float4 b1 = ((const float4*)bias)[q * 2 + 1];
        float r0 = fmaxf(acc[0] * di + b0.x, 0.f);
        float r1 = fmaxf(acc[1] * di + b0.y, 0.f);
        float r2 = fmaxf(acc[2] * di + b0.z, 0.f);
        float r3 = fmaxf(acc[3] * di + b0.w, 0.f);
        float r4 = fmaxf(acc[4] * di + b1.x, 0.f);
        float r5 = fmaxf(acc[5] * di + b1.y, 0.f);
        float r6 = fmaxf(acc[6] * di + b1.z, 0.f);
        float r7 = fmaxf(acc[7] * di + b1.w, 0.f);
        uint4 ov;
        *(__half2*)&ov.x = __floats2half2_rn(r0, r1);
        *(__half2*)&ov.y = __floats2half2_rn(r2, r3);
        *(__half2*)&ov.z = __floats2half2_rn(r4, r5);
        *(__half2*)&ov.w = __floats2half2_rn(r6, r7);
        ((uint4*)out)[(size_t)node * 16 + q] = ov;
    }
}

// ------- aggregation C=64 + bias + fused mean-pool accumulation ------------
// Row = 128B. Each lane loads uint4; quarter-warp covers a row => 4 edges per
// warp load. shfl_xor(8) + shfl_xor(16) combine; lanes 0-7 do pool atomics.
__global__ void k_agg64_pool(const __half* __restrict__ h,
                             const float* __restrict__ bias,
                             const int* __restrict__ batch) {
    int node = (blockIdx.x * blockDim.x + threadIdx.x) >> 5;
    if (node >= NN) return;
    int lane = threadIdx.x & 31;
    int quad = lane >> 3;        // 0..3 : which edge of the quad
    int q    = lane & 7;         // 16B chunk within row
    const uint4* hv = (const uint4*)h;   // 8 uint4 per row

    int beg = g_rowstart[node];
    int cnt = g_rowstart[node + 1] - beg + 1;   // +1 virtual self
    float di = g_dinv[node];

    float acc[8];
    #pragma unroll
    for (int j = 0; j < 8; j++) acc[j] = 0.f;

    for (int base = 0; base < cnt; base += 8) {
        #pragma unroll
        for (int u = 0; u < 2; u++) {
            int t = base + u * 4 + quad;
            if (t < cnt) {
                int s = (t == 0) ? node : g_csr_src[beg + t - 1];
                acc_uint4(acc, hv[(size_t)s * 8 + q]);
            }
        }
    }
    #pragma unroll
    for (int j = 0; j < 8; j++) {
        acc[j] += __shfl_xor_sync(0xffffffffu, acc[j], 8);
        acc[j] += __shfl_xor_sync(0xffffffffu, acc[j], 16);
    }

    if (lane < 8) {
        int g = batch[node];
        #pragma unroll
        for (int j = 0; j < 8; j++) {
            float val = acc[j] * di + bias[q * 8 + j];
            atomicAdd(&g_pool[g * C_OUT + q * 8 + j], val);
        }
    }
}

// final: divide pooled sums by per-graph node counts
__global__ void k_final(const int* __restrict__ batch,
                        float* __restrict__ out) {
    int idx = blockIdx.x * blockDim.x + threadIdx.x;
    if (idx >= NG * C_OUT) return;
    int g = idx >> 6;
    int lo = lower_bound_i32(batch, NN, g);
    int hi = lower_bound_i32(batch, NN, g + 1);
    float cnt = (float)(hi - lo);
    out[idx] = g_pool[idx] / fmaxf(cnt, 1.0f);
}

// ------------------------------ launch -------------------------------------
extern "C" void kernel_launch(void* const* d_in, const int* in_sizes, int n_in,
                              void* d_out, int out_size) {
    const float* x     = (const float*)d_in[0];
    const float* W1    = (const float*)d_in[1];
    const float* b1    = (const float*)d_in[2];
    const float* W2    = (const float*)d_in[3];
    const float* b2    = (const float*)d_in[4];
    const int*   ei    = (const int*)d_in[5];
    const int*   batch = (const int*)d_in[6];
    float* out = (float*)d_out;

    __half *h1, *g1, *h2;
    void *degp, *poolp;
    cudaGetSymbolAddress((void**)&h1, g_h1);
    cudaGetSymbolAddress((void**)&g1, g_g1);
    cudaGetSymbolAddress((void**)&h2, g_h2);
    cudaGetSymbolAddress(&degp, g_deg);
    cudaGetSymbolAddress(&poolp, g_pool);

    const int TB  = 256;
    const int gN  = (NN + TB - 1) / TB;           // 196
    const int gE4 = (NE / 4 + TB - 1) / TB;       // 586
    const int gM  = (NN + 127) / 128;             // 391
    const int gAg = (NN + 7) / 8;                 // 6250

    cudaMemsetAsync(degp, 0, NN * sizeof(int));
    cudaMemsetAsync(poolp, 0, NG * C_OUT * sizeof(float));
    k_deg<<<gE4, TB>>>(ei);
    k_scanA<<<NCHUNK, 256>>>();
    k_scanC<<<gN, TB>>>();
    k_fill<<<gE4, TB>>>(ei);

    k_gemm_tf32<128, float><<<gM, 256>>>(x, W1, h1, NN);
    k_agg128<<<gAg, TB>>>(h1, b1, g1);
    k_gemm_tf32<64, __half><<<gM, 256>>>(g1, W2, h2, NN);
    k_agg64_pool<<<gAg, TB>>>(h2, b2, batch);
    k_final<<<(NG * C_OUT + TB - 1) / TB, TB>>>(batch, out);
}